// round 6
// baseline (speedup 1.0000x reference)
#include <cuda_runtime.h>
#include <cuda_bf16.h>
#include <mma.h>
#include <cstdint>
#include <cstring>

using namespace nvcuda;

#define T_DIM   2048
#define B_DIM   128
#define IN_DIM  64
#define H_DIM   128
#define G_DIM   512
#define OUT_DIM 32
#define M_TOT   (T_DIM * B_DIM)   // 262144

typedef unsigned long long ull;

// scratch (device globals: allocation-free per harness rules)
__device__ float g_xp[(size_t)M_TOT * G_DIM];  // 512 MB, reused by both layers
__device__ float g_y [(size_t)M_TOT * H_DIM];  // 128 MB, layer outputs (y0 then y1)

// ---------------- activations ------------------------------------------------
__device__ __forceinline__ float tanh_f(float x) {
    float y; asm("tanh.approx.f32 %0, %1;" : "=f"(y) : "f"(x)); return y;
}
__device__ __forceinline__ float sigmoid_f(float x) {
    return 0.5f * tanh_f(0.5f * x) + 0.5f;
}
__device__ __forceinline__ ull fma2(ull a, ull b, ull c) {
    ull d; asm("fma.rn.f32x2 %0, %1, %2, %3;" : "=l"(d) : "l"(a), "l"(b), "l"(c));
    return d;
}
__device__ __forceinline__ float lo32(ull v) { return __uint_as_float((unsigned)(v & 0xffffffffu)); }
__device__ __forceinline__ float hi32(ull v) { return __uint_as_float((unsigned)(v >> 32)); }

// =============================================================================
// Persistent bf16(hi+lo) tensor-core GEMM: C[m][g] = sum_k A[m][k]*W[g][k]
// Grid (8 n-tiles of 64, GY). Each CTA: stage its W rows ONCE (bf16 hi/lo),
// then stream m-tiles of 64 rows with double-buffered smem + reg prefetch.
// 3-term bf16 MMA: ah*bh + al*bh + ah*bl (al*bl ~2^-18, dropped).
// =============================================================================
#define GEMM_GY 18

template<int K>
__global__ void __launch_bounds__(256) gemm_bf3p(const float* __restrict__ A,
                                                 const float* __restrict__ W,
                                                 float* __restrict__ C)
{
    constexpr int LD  = K + 8;
    constexpr int NPF = K / 16;           // float4 loads per thread per 64-row tile
    constexpr int F4R = K / 4;            // float4 per row
    constexpr int MT_TOT = M_TOT / 64;    // 4096 m-tiles

    extern __shared__ __nv_bfloat16 sb[];
    __nv_bfloat16* Wh = sb;                         // [64][LD]
    __nv_bfloat16* Wl = Wh + 64 * LD;               // [64][LD]
    __nv_bfloat16* Ab = Wl + 64 * LD;               // 2 bufs x (Ah[64][LD], Al[64][LD])

    const int tid = threadIdx.x;
    const int n0  = blockIdx.x * 64;

    // ---- stage W once ----
    #pragma unroll
    for (int u = 0; u < NPF; u++) {
        int idx = tid + u * 256;
        int r = idx / F4R, cq = idx % F4R;
        float4 v = *reinterpret_cast<const float4*>(W + (size_t)(n0 + r) * K + cq * 4);
        __nv_bfloat162 h0, h1, l0, l1;
        h0.x = __float2bfloat16_rn(v.x); h0.y = __float2bfloat16_rn(v.y);
        h1.x = __float2bfloat16_rn(v.z); h1.y = __float2bfloat16_rn(v.w);
        l0.x = __float2bfloat16_rn(v.x - __bfloat162float(h0.x));
        l0.y = __float2bfloat16_rn(v.y - __bfloat162float(h0.y));
        l1.x = __float2bfloat16_rn(v.z - __bfloat162float(h1.x));
        l1.y = __float2bfloat16_rn(v.w - __bfloat162float(h1.y));
        union { __nv_bfloat162 b[2]; uint2 u2; } ph, pl;
        ph.b[0] = h0; ph.b[1] = h1; pl.b[0] = l0; pl.b[1] = l1;
        *reinterpret_cast<uint2*>(Wh + r * LD + cq * 4) = ph.u2;
        *reinterpret_cast<uint2*>(Wl + r * LD + cq * 4) = pl.u2;
    }

    const int warp = tid >> 5;
    const int wm = warp >> 1, wn = warp & 1;   // 4 m-warps x 2 n-warps

    // ---- prologue: stage first A tile into buf 0 ----
    int mt = blockIdx.y;
    {
        #pragma unroll
        for (int u = 0; u < NPF; u++) {
            int idx = tid + u * 256;
            int r = idx / F4R, cq = idx % F4R;
            float4 v = *reinterpret_cast<const float4*>(A + (size_t)(mt * 64 + r) * K + cq * 4);
            __nv_bfloat162 h0, h1, l0, l1;
            h0.x = __float2bfloat16_rn(v.x); h0.y = __float2bfloat16_rn(v.y);
            h1.x = __float2bfloat16_rn(v.z); h1.y = __float2bfloat16_rn(v.w);
            l0.x = __float2bfloat16_rn(v.x - __bfloat162float(h0.x));
            l0.y = __float2bfloat16_rn(v.y - __bfloat162float(h0.y));
            l1.x = __float2bfloat16_rn(v.z - __bfloat162float(h1.x));
            l1.y = __float2bfloat16_rn(v.w - __bfloat162float(h1.y));
            union { __nv_bfloat162 b[2]; uint2 u2; } ph, pl;
            ph.b[0] = h0; ph.b[1] = h1; pl.b[0] = l0; pl.b[1] = l1;
            *reinterpret_cast<uint2*>(Ab + r * LD + cq * 4) = ph.u2;
            *reinterpret_cast<uint2*>(Ab + 64 * LD + r * LD + cq * 4) = pl.u2;
        }
    }
    __syncthreads();

    int buf = 0;
    while (mt < MT_TOT) {
        const int mtn = mt + GEMM_GY;
        const bool has_next = mtn < MT_TOT;

        // issue next tile's global loads NOW (hidden under the MMA loop)
        float4 pf[NPF];
        if (has_next) {
            #pragma unroll
            for (int u = 0; u < NPF; u++) {
                int idx = tid + u * 256;
                int r = idx / F4R, cq = idx % F4R;
                pf[u] = *reinterpret_cast<const float4*>(A + (size_t)(mtn * 64 + r) * K + cq * 4);
            }
        }

        // MMA on current buffer
        __nv_bfloat16* Ah = Ab + buf * (2 * 64 * LD);
        __nv_bfloat16* Al = Ah + 64 * LD;
        wmma::fragment<wmma::accumulator, 16, 16, 16, float> c[2];
        wmma::fill_fragment(c[0], 0.0f);
        wmma::fill_fragment(c[1], 0.0f);
        #pragma unroll
        for (int k = 0; k < K; k += 16) {
            wmma::fragment<wmma::matrix_a, 16, 16, 16, __nv_bfloat16, wmma::row_major> fah, fal;
            wmma::load_matrix_sync(fah, Ah + (wm * 16) * LD + k, LD);
            wmma::load_matrix_sync(fal, Al + (wm * 16) * LD + k, LD);
            #pragma unroll
            for (int jj = 0; jj < 2; jj++) {
                wmma::fragment<wmma::matrix_b, 16, 16, 16, __nv_bfloat16, wmma::col_major> fbh, fbl;
                wmma::load_matrix_sync(fbh, Wh + (wn * 32 + 16 * jj) * LD + k, LD);
                wmma::load_matrix_sync(fbl, Wl + (wn * 32 + 16 * jj) * LD + k, LD);
                wmma::mma_sync(c[jj], fal, fbh, c[jj]);
                wmma::mma_sync(c[jj], fah, fbl, c[jj]);
                wmma::mma_sync(c[jj], fah, fbh, c[jj]);
            }
        }

        // stage next tile into the other buffer
        if (has_next) {
            __nv_bfloat16* Dh = Ab + (buf ^ 1) * (2 * 64 * LD);
            __nv_bfloat16* Dl = Dh + 64 * LD;
            #pragma unroll
            for (int u = 0; u < NPF; u++) {
                int idx = tid + u * 256;
                int r = idx / F4R, cq = idx % F4R;
                float4 v = pf[u];
                __nv_bfloat162 h0, h1, l0, l1;
                h0.x = __float2bfloat16_rn(v.x); h0.y = __float2bfloat16_rn(v.y);
                h1.x = __float2bfloat16_rn(v.z); h1.y = __float2bfloat16_rn(v.w);
                l0.x = __float2bfloat16_rn(v.x - __bfloat162float(h0.x));
                l0.y = __float2bfloat16_rn(v.y - __bfloat162float(h0.y));
                l1.x = __float2bfloat16_rn(v.z - __bfloat162float(h1.x));
                l1.y = __float2bfloat16_rn(v.w - __bfloat162float(h1.y));
                union { __nv_bfloat162 b[2]; uint2 u2; } ph, pl;
                ph.b[0] = h0; ph.b[1] = h1; pl.b[0] = l0; pl.b[1] = l1;
                *reinterpret_cast<uint2*>(Dh + r * LD + cq * 4) = ph.u2;
                *reinterpret_cast<uint2*>(Dl + r * LD + cq * 4) = pl.u2;
            }
        }
        __syncthreads();

        // epilogue: store C for this m-tile
        #pragma unroll
        for (int jj = 0; jj < 2; jj++)
            wmma::store_matrix_sync(C + (size_t)(mt * 64 + wm * 16) * G_DIM + n0 + wn * 32 + 16 * jj,
                                    c[jj], G_DIM, wmma::mem_row_major);

        buf ^= 1;
        mt = mtn;
    }
}

// =============================================================================
// Persistent per-batch LSTM recurrence — 1 barrier/step, shfl gate exchange.
// grid = 128 CTAs (one per batch), 256 threads.
// Warp w, lane l: cell m = w*16 + (l&15).
//   lanes l<16 : rows (m)      [i-gate] and (256+m) [g-gate]
//   lanes l>=16: rows (128+m)  [f-gate] and (384+m) [o-gate]
// Activations swapped between the pair with 2x shfl_xor(16); both lanes
// redundantly compute identical c,h (bit-deterministic). Double-buffered h_s
// means one __syncthreads per step.
// Weights: k in [0,96) in 48 b64 regs/row; k in [96,128) in smem ws2[c][row].
// =============================================================================
#define REC_SMEM (65536 + 2 * 128 * 4)

__global__ void __launch_bounds__(256, 1) lstm_rec(const float* __restrict__ xp,
                                                   const float* __restrict__ whh,
                                                   float* __restrict__ y,
                                                   float* __restrict__ hn,
                                                   float* __restrict__ cn)
{
    extern __shared__ __align__(16) char smraw[];
    ulonglong2* ws2 = reinterpret_cast<ulonglong2*>(smraw);       // [8][512]
    float*      hsb = reinterpret_cast<float*>(smraw + 65536);    // [2][128]

    const int b    = blockIdx.x;
    const int tid  = threadIdx.x;
    const int lane = tid & 31;
    const int w    = tid >> 5;
    const int half = lane >> 4;               // 0: i/g rows, 1: f/o rows
    const int m    = w * 16 + (lane & 15);

    const int rowA = half ? (128 + m) : m;          // f : i
    const int rowB = half ? (384 + m) : (256 + m);  // o : g

    // ---- load weights ----
    const ull* wrowA = reinterpret_cast<const ull*>(whh + (size_t)rowA * H_DIM);
    const ull* wrowB = reinterpret_cast<const ull*>(whh + (size_t)rowB * H_DIM);
    ull wa[48], wb[48];
    #pragma unroll
    for (int u = 0; u < 48; u++) { wa[u] = wrowA[u]; wb[u] = wrowB[u]; }
    const ulonglong2* wrA2 = reinterpret_cast<const ulonglong2*>(wrowA);
    const ulonglong2* wrB2 = reinterpret_cast<const ulonglong2*>(wrowB);
    #pragma unroll
    for (int c = 0; c < 8; c++) {
        ws2[c * 512 + rowA] = wrA2[24 + c];
        ws2[c * 512 + rowB] = wrB2[24 + c];
    }
    if (tid < H_DIM) hsb[tid] = 0.0f;         // h buffer 0 = zeros
    float cst = 0.0f, h_last = 0.0f;
    __syncthreads();

    const float* xpA = xp + (size_t)b * G_DIM + rowA;
    const float* xpB = xp + (size_t)b * G_DIM + rowB;
    float xvA = xpA[0], xvB = xpB[0];

    for (int t = 0; t < T_DIM; t++) {
        const float* rd = hsb + (t & 1) * 128;
        float*       wr = hsb + ((t + 1) & 1) * 128;
        const ulonglong2* h22 = reinterpret_cast<const ulonglong2*>(rd);

        float xnA = 0.0f, xnB = 0.0f;
        if (t + 1 < T_DIM) {
            size_t off = (size_t)(t + 1) * B_DIM * G_DIM;
            xnA = xpA[off]; xnB = xpB[off];
        }

        ull aA0 = 0, aA1 = 0, aB0 = 0, aB1 = 0;
        #pragma unroll
        for (int c = 0; c < 24; c++) {               // k 0..95: reg weights
            ulonglong2 hv = h22[c];
            aA0 = fma2(wa[2 * c],     hv.x, aA0);
            aA1 = fma2(wa[2 * c + 1], hv.y, aA1);
            aB0 = fma2(wb[2 * c],     hv.x, aB0);
            aB1 = fma2(wb[2 * c + 1], hv.y, aB1);
        }
        #pragma unroll
        for (int c = 0; c < 8; c++) {                // k 96..127: smem weights
            ulonglong2 hv  = h22[24 + c];
            ulonglong2 wvA = ws2[c * 512 + rowA];
            ulonglong2 wvB = ws2[c * 512 + rowB];
            aA0 = fma2(wvA.x, hv.x, aA0);
            aA1 = fma2(wvA.y, hv.y, aA1);
            aB0 = fma2(wvB.x, hv.x, aB0);
            aB1 = fma2(wvB.y, hv.y, aB1);
        }
        float gA = xvA + ((lo32(aA0) + hi32(aA0)) + (lo32(aA1) + hi32(aA1)));
        float gB = xvB + ((lo32(aB0) + hi32(aB0)) + (lo32(aB1) + hi32(aB1)));

        // lane<16: a1 = i, a2 = g ; lane>=16: a1 = f, a2 = o
        float a1 = sigmoid_f(gA);
        float a2 = half ? sigmoid_f(gB) : tanh_f(gB);
        float p1 = __shfl_xor_sync(0xffffffffu, a1, 16);
        float p2 = __shfl_xor_sync(0xffffffffu, a2, 16);

        float ig = half ? p1 : a1;
        float gg = half ? p2 : a2;
        float fg = half ? a1 : p1;
        float og = half ? a2 : p2;

        cst = fg * cst + ig * gg;
        float h = og * tanh_f(cst);
        h_last = h;
        if (!half) {
            wr[m] = h;
            y[((size_t)t * B_DIM + b) * H_DIM + m] = h;
        }
        __syncthreads();
        xvA = xnA; xvB = xnB;
    }
    if (!half) {
        hn[b * H_DIM + m] = h_last;
        cn[b * H_DIM + m] = cst;
    }
}

// ---------------- FC head: out[m][o] = sum_k y[m][k]*fc_w[o][k] + b[o] ------
__global__ void __launch_bounds__(256) fc_head(const float* __restrict__ A,
                                               const float* __restrict__ W,
                                               const float* __restrict__ bias,
                                               float* __restrict__ C)
{
    __shared__ float ys[32][128];
    __shared__ float wst[128][32];
    const int tid = threadIdx.x;
    const int m0 = blockIdx.x * 32;

    for (int i = tid; i < OUT_DIM * H_DIM; i += 256) {
        int o = i / H_DIM, k = i % H_DIM;
        wst[k][o] = W[i];
    }
    for (int i = tid; i < 32 * H_DIM; i += 256) {
        int r = i / H_DIM, k = i % H_DIM;
        ys[r][k] = A[(size_t)(m0 + r) * H_DIM + k];
    }
    __syncthreads();

    const int o = tid & 31, mq = tid >> 5;
    float a0 = 0.f, a1 = 0.f, a2 = 0.f, a3 = 0.f;
    #pragma unroll 8
    for (int k = 0; k < H_DIM; k++) {
        float w = wst[k][o];
        a0 += ys[mq * 4 + 0][k] * w;
        a1 += ys[mq * 4 + 1][k] * w;
        a2 += ys[mq * 4 + 2][k] * w;
        a3 += ys[mq * 4 + 3][k] * w;
    }
    float bb = bias[o];
    C[(size_t)(m0 + mq * 4 + 0) * OUT_DIM + o] = a0 + bb;
    C[(size_t)(m0 + mq * 4 + 1) * OUT_DIM + o] = a1 + bb;
    C[(size_t)(m0 + mq * 4 + 2) * OUT_DIM + o] = a2 + bb;
    C[(size_t)(m0 + mq * 4 + 3) * OUT_DIM + o] = a3 + bb;
}

extern "C" void kernel_launch(void* const* d_in, const int* in_sizes, int n_in,
                              void* d_out, int out_size)
{
    const float* x     = (const float*)d_in[0];
    const float* w_ih0 = (const float*)d_in[1];
    const float* w_hh0 = (const float*)d_in[2];
    const float* w_ih1 = (const float*)d_in[3];
    const float* w_hh1 = (const float*)d_in[4];
    const float* fc_w  = (const float*)d_in[5];
    const float* fc_b  = (const float*)d_in[6];
    float* out = (float*)d_out;

    float* xp; cudaGetSymbolAddress((void**)&xp, g_xp);
    float* y;  cudaGetSymbolAddress((void**)&y,  g_y);

    float* hn = out + (size_t)M_TOT * OUT_DIM;            // [2,128,128]
    float* cn = hn + 2 * B_DIM * H_DIM;                   // [2,128,128]

    constexpr int SMEM64  = 768 * (64 + 8);    // 55,296 B
    constexpr int SMEM128 = 768 * (128 + 8);   // 104,448 B

    static bool attr_done = false;
    if (!attr_done) {
        cudaFuncSetAttribute(lstm_rec, cudaFuncAttributeMaxDynamicSharedMemorySize, REC_SMEM);
        cudaFuncSetAttribute(gemm_bf3p<IN_DIM>, cudaFuncAttributeMaxDynamicSharedMemorySize, SMEM64);
        cudaFuncSetAttribute(gemm_bf3p<H_DIM>,  cudaFuncAttributeMaxDynamicSharedMemorySize, SMEM128);
        attr_done = true;
    }

    dim3 gg(G_DIM / 64, GEMM_GY);
    // layer 0
    gemm_bf3p<IN_DIM><<<gg, 256, SMEM64>>>(x, w_ih0, xp);
    lstm_rec<<<B_DIM, 256, REC_SMEM>>>(xp, w_hh0, y, hn, cn);
    // layer 1
    gemm_bf3p<H_DIM><<<gg, 256, SMEM128>>>(y, w_ih1, xp);
    lstm_rec<<<B_DIM, 256, REC_SMEM>>>(xp, w_hh1, y, hn + B_DIM * H_DIM, cn + B_DIM * H_DIM);
    // FC head
    fc_head<<<M_TOT / 32, 256>>>(y, fc_w, fc_b, out);
}

// round 7
// speedup vs baseline: 1.4816x; 1.4816x over previous
#include <cuda_runtime.h>
#include <cuda_bf16.h>
#include <mma.h>
#include <cstdint>

using namespace nvcuda;

#define T_DIM   2048
#define B_DIM   128
#define IN_DIM  64
#define H_DIM   128
#define G_DIM   512
#define OUT_DIM 32
#define M_TOT   (T_DIM * B_DIM)   // 262144

typedef unsigned long long ull;

// scratch (device globals: allocation-free per harness rules)
__device__ __align__(16) float g_xp[(size_t)M_TOT * G_DIM];          // 512 MB
__device__ __align__(16) float g_y [(size_t)M_TOT * H_DIM];          // 128 MB
__device__ __align__(16) __nv_bfloat16 g_ah[(size_t)M_TOT * H_DIM];  // 64 MB (A hi)
__device__ __align__(16) __nv_bfloat16 g_al[(size_t)M_TOT * H_DIM];  // 64 MB (A lo)
__device__ __align__(16) __nv_bfloat16 g_wh[G_DIM * H_DIM];          // W hi
__device__ __align__(16) __nv_bfloat16 g_wl[G_DIM * H_DIM];          // W lo

// ---------------- activations ------------------------------------------------
__device__ __forceinline__ float tanh_f(float x) {
    float y; asm("tanh.approx.f32 %0, %1;" : "=f"(y) : "f"(x)); return y;
}
__device__ __forceinline__ float sigmoid_f(float x) {
    return 0.5f * tanh_f(0.5f * x) + 0.5f;
}
__device__ __forceinline__ ull fma2(ull a, ull b, ull c) {
    ull d; asm("fma.rn.f32x2 %0, %1, %2, %3;" : "=l"(d) : "l"(a), "l"(b), "l"(c));
    return d;
}
__device__ __forceinline__ float lo32(ull v) { return __uint_as_float((unsigned)(v & 0xffffffffu)); }
__device__ __forceinline__ float hi32(ull v) { return __uint_as_float((unsigned)(v >> 32)); }

// ---------------- fp32 -> bf16 hi/lo split (one elementwise pass) -----------
__global__ void __launch_bounds__(256) conv_hl(const float* __restrict__ src,
                                               __nv_bfloat16* __restrict__ dh,
                                               __nv_bfloat16* __restrict__ dl,
                                               int n4)
{
    int i = blockIdx.x * 256 + threadIdx.x;
    if (i >= n4) return;
    float4 v = reinterpret_cast<const float4*>(src)[i];
    __nv_bfloat162 h0, h1, l0, l1;
    h0.x = __float2bfloat16_rn(v.x); h0.y = __float2bfloat16_rn(v.y);
    h1.x = __float2bfloat16_rn(v.z); h1.y = __float2bfloat16_rn(v.w);
    l0.x = __float2bfloat16_rn(v.x - __bfloat162float(h0.x));
    l0.y = __float2bfloat16_rn(v.y - __bfloat162float(h0.y));
    l1.x = __float2bfloat16_rn(v.z - __bfloat162float(h1.x));
    l1.y = __float2bfloat16_rn(v.w - __bfloat162float(h1.y));
    union { __nv_bfloat162 b[2]; uint2 u2; } ph, pl;
    ph.b[0] = h0; ph.b[1] = h1; pl.b[0] = l0; pl.b[1] = l1;
    reinterpret_cast<uint2*>(dh)[i] = ph.u2;
    reinterpret_cast<uint2*>(dl)[i] = pl.u2;
}

// ---------------- bf16(hi+lo) tensor-core GEMM (pre-split inputs) -----------
// C[m][g] = sum_k A[m][k]*W[g][k]; 3 terms ah*bh + al*bh + ah*bl.
// Block tile 128x64, 256 thr = 8 warps (4 m x 2 n), warp tile 32x32.
// Staging is pure uint4 copies (conversion hoisted to conv_hl).
template<int K>
__global__ void __launch_bounds__(256) gemm_bf(const __nv_bfloat16* __restrict__ Ah,
                                               const __nv_bfloat16* __restrict__ Al,
                                               const __nv_bfloat16* __restrict__ Wh,
                                               const __nv_bfloat16* __restrict__ Wl,
                                               float* __restrict__ C)
{
    constexpr int LD  = K + 8;
    constexpr int V8  = K / 8;                // uint4 (8 bf16) per row
    extern __shared__ __nv_bfloat16 sb[];
    __nv_bfloat16* Ahs = sb;                  // [128][LD]
    __nv_bfloat16* Als = Ahs + 128 * LD;
    __nv_bfloat16* Whs = Als + 128 * LD;      // [64][LD]
    __nv_bfloat16* Wls = Whs + 64 * LD;

    const int tid = threadIdx.x;
    const int m0 = blockIdx.y * 128, n0 = blockIdx.x * 64;

    #pragma unroll
    for (int i = tid; i < 128 * V8; i += 256) {
        int r = i / V8, c = i % V8;
        reinterpret_cast<uint4*>(Ahs + r * LD)[c] =
            *reinterpret_cast<const uint4*>(Ah + (size_t)(m0 + r) * K + c * 8);
        reinterpret_cast<uint4*>(Als + r * LD)[c] =
            *reinterpret_cast<const uint4*>(Al + (size_t)(m0 + r) * K + c * 8);
    }
    #pragma unroll
    for (int i = tid; i < 64 * V8; i += 256) {
        int r = i / V8, c = i % V8;
        reinterpret_cast<uint4*>(Whs + r * LD)[c] =
            *reinterpret_cast<const uint4*>(Wh + (size_t)(n0 + r) * K + c * 8);
        reinterpret_cast<uint4*>(Wls + r * LD)[c] =
            *reinterpret_cast<const uint4*>(Wl + (size_t)(n0 + r) * K + c * 8);
    }
    __syncthreads();

    const int warp = tid >> 5;
    const int wm = warp >> 1, wn = warp & 1;

    wmma::fragment<wmma::accumulator, 16, 16, 16, float> c[2][2];
    #pragma unroll
    for (int i = 0; i < 2; i++)
        #pragma unroll
        for (int j = 0; j < 2; j++) wmma::fill_fragment(c[i][j], 0.0f);

    #pragma unroll
    for (int k = 0; k < K; k += 16) {
        wmma::fragment<wmma::matrix_a, 16, 16, 16, __nv_bfloat16, wmma::row_major> fah[2], fal[2];
        wmma::fragment<wmma::matrix_b, 16, 16, 16, __nv_bfloat16, wmma::col_major> fbh[2], fbl[2];
        #pragma unroll
        for (int i = 0; i < 2; i++) {
            wmma::load_matrix_sync(fah[i], Ahs + (wm * 32 + 16 * i) * LD + k, LD);
            wmma::load_matrix_sync(fal[i], Als + (wm * 32 + 16 * i) * LD + k, LD);
            wmma::load_matrix_sync(fbh[i], Whs + (wn * 32 + 16 * i) * LD + k, LD);
            wmma::load_matrix_sync(fbl[i], Wls + (wn * 32 + 16 * i) * LD + k, LD);
        }
        #pragma unroll
        for (int i = 0; i < 2; i++)
            #pragma unroll
            for (int j = 0; j < 2; j++) {
                wmma::mma_sync(c[i][j], fal[i], fbh[j], c[i][j]);
                wmma::mma_sync(c[i][j], fah[i], fbl[j], c[i][j]);
                wmma::mma_sync(c[i][j], fah[i], fbh[j], c[i][j]);
            }
    }
    #pragma unroll
    for (int i = 0; i < 2; i++)
        #pragma unroll
        for (int j = 0; j < 2; j++)
            wmma::store_matrix_sync(C + (size_t)(m0 + wm * 32 + 16 * i) * G_DIM + (n0 + wn * 32 + 16 * j),
                                    c[i][j], G_DIM, wmma::mem_row_major);
}

// =============================================================================
// Persistent per-batch LSTM recurrence (R5 version — proven fastest).
// grid = 128 CTAs, 256 threads; thread j owns gate rows j and j+256.
// Weights: k in [0,96) in 48 b64 regs/row; k in [96,128) in smem ws2[c][row].
// =============================================================================
#define REC_SMEM (65536 + 128 * 4 * 3)

__global__ void __launch_bounds__(256, 1) lstm_rec(const float* __restrict__ xp,
                                                   const float* __restrict__ whh,
                                                   float* __restrict__ y,
                                                   float* __restrict__ hn,
                                                   float* __restrict__ cn)
{
    extern __shared__ __align__(16) char smraw[];
    ulonglong2* ws2  = reinterpret_cast<ulonglong2*>(smraw);      // [8][512]
    float*      h_s  = reinterpret_cast<float*>(smraw + 65536);   // [128]
    float*      fsig = h_s + 128;                                  // [128]
    float*      osig = fsig + 128;                                 // [128]

    const int b  = blockIdx.x;
    const int j  = threadIdx.x;           // 0..255
    const int rA = j;
    const int rB = j + 256;

    const ull* wrowA = reinterpret_cast<const ull*>(whh + (size_t)rA * H_DIM);
    const ull* wrowB = reinterpret_cast<const ull*>(whh + (size_t)rB * H_DIM);
    ull wa[48], wb[48];
    #pragma unroll
    for (int u = 0; u < 48; u++) { wa[u] = wrowA[u]; wb[u] = wrowB[u]; }
    const ulonglong2* wrA2 = reinterpret_cast<const ulonglong2*>(wrowA);
    const ulonglong2* wrB2 = reinterpret_cast<const ulonglong2*>(wrowB);
    #pragma unroll
    for (int c = 0; c < 8; c++) {
        ws2[c * 512 + rA] = wrA2[24 + c];
        ws2[c * 512 + rB] = wrB2[24 + c];
    }
    if (j < H_DIM) h_s[j] = 0.0f;
    float cst = 0.0f;
    __syncthreads();

    const float* xpA = xp + (size_t)b * G_DIM + rA;
    const float* xpB = xp + (size_t)b * G_DIM + rB;
    float xvA = xpA[0], xvB = xpB[0];
    const ulonglong2* h22 = reinterpret_cast<const ulonglong2*>(h_s);

    for (int t = 0; t < T_DIM; t++) {
        float xnA = 0.0f, xnB = 0.0f;
        if (t + 1 < T_DIM) {
            size_t off = (size_t)(t + 1) * B_DIM * G_DIM;
            xnA = xpA[off]; xnB = xpB[off];
        }

        ull aA0 = 0, aA1 = 0, aB0 = 0, aB1 = 0;
        #pragma unroll
        for (int c = 0; c < 24; c++) {               // k 0..95: reg weights
            ulonglong2 hv = h22[c];
            aA0 = fma2(wa[2 * c],     hv.x, aA0);
            aA1 = fma2(wa[2 * c + 1], hv.y, aA1);
            aB0 = fma2(wb[2 * c],     hv.x, aB0);
            aB1 = fma2(wb[2 * c + 1], hv.y, aB1);
        }
        #pragma unroll
        for (int c = 0; c < 8; c++) {                // k 96..127: smem weights
            ulonglong2 hv  = h22[24 + c];
            ulonglong2 wvA = ws2[c * 512 + rA];
            ulonglong2 wvB = ws2[c * 512 + rB];
            aA0 = fma2(wvA.x, hv.x, aA0);
            aA1 = fma2(wvA.y, hv.y, aA1);
            aB0 = fma2(wvB.x, hv.x, aB0);
            aB1 = fma2(wvB.y, hv.y, aB1);
        }
        float gA = xvA + ((lo32(aA0) + hi32(aA0)) + (lo32(aA1) + hi32(aA1)));
        float gB = xvB + ((lo32(aB0) + hi32(aB0)) + (lo32(aB1) + hi32(aB1)));

        float iact = 0.0f, gact = 0.0f;
        if (j < 128) {                   // rows j (i) and j+256 (g)
            iact = sigmoid_f(gA);
            gact = tanh_f(gB);
        } else {                         // rows 128+m (f) and 384+m (o)
            fsig[j - 128] = sigmoid_f(gA);
            osig[j - 128] = sigmoid_f(gB);
        }
        __syncthreads();
        if (j < 128) {
            cst = fsig[j] * cst + iact * gact;
            float h = osig[j] * tanh_f(cst);
            h_s[j] = h;
            y[((size_t)t * B_DIM + b) * H_DIM + j] = h;
        }
        __syncthreads();
        xvA = xnA; xvB = xnB;
    }
    if (j < 128) {
        hn[b * H_DIM + j] = h_s[j];
        cn[b * H_DIM + j] = cst;
    }
}

// ---------------- FC head: out[m][o] = sum_k y[m][k]*fc_w[o][k] + b[o] ------
__global__ void __launch_bounds__(256) fc_head(const float* __restrict__ A,
                                               const float* __restrict__ W,
                                               const float* __restrict__ bias,
                                               float* __restrict__ C)
{
    __shared__ float ys[32][128];
    __shared__ float wst[128][32];
    const int tid = threadIdx.x;
    const int m0 = blockIdx.x * 32;

    for (int i = tid; i < OUT_DIM * H_DIM; i += 256) {
        int o = i / H_DIM, k = i % H_DIM;
        wst[k][o] = W[i];
    }
    for (int i = tid; i < 32 * H_DIM; i += 256) {
        int r = i / H_DIM, k = i % H_DIM;
        ys[r][k] = A[(size_t)(m0 + r) * H_DIM + k];
    }
    __syncthreads();

    const int o = tid & 31, mq = tid >> 5;
    float a0 = 0.f, a1 = 0.f, a2 = 0.f, a3 = 0.f;
    #pragma unroll 8
    for (int k = 0; k < H_DIM; k++) {
        float w = wst[k][o];
        a0 += ys[mq * 4 + 0][k] * w;
        a1 += ys[mq * 4 + 1][k] * w;
        a2 += ys[mq * 4 + 2][k] * w;
        a3 += ys[mq * 4 + 3][k] * w;
    }
    float bb = bias[o];
    C[(size_t)(m0 + mq * 4 + 0) * OUT_DIM + o] = a0 + bb;
    C[(size_t)(m0 + mq * 4 + 1) * OUT_DIM + o] = a1 + bb;
    C[(size_t)(m0 + mq * 4 + 2) * OUT_DIM + o] = a2 + bb;
    C[(size_t)(m0 + mq * 4 + 3) * OUT_DIM + o] = a3 + bb;
}

extern "C" void kernel_launch(void* const* d_in, const int* in_sizes, int n_in,
                              void* d_out, int out_size)
{
    const float* x     = (const float*)d_in[0];
    const float* w_ih0 = (const float*)d_in[1];
    const float* w_hh0 = (const float*)d_in[2];
    const float* w_ih1 = (const float*)d_in[3];
    const float* w_hh1 = (const float*)d_in[4];
    const float* fc_w  = (const float*)d_in[5];
    const float* fc_b  = (const float*)d_in[6];
    float* out = (float*)d_out;

    float* xp; cudaGetSymbolAddress((void**)&xp, g_xp);
    float* y;  cudaGetSymbolAddress((void**)&y,  g_y);
    __nv_bfloat16 *ah, *al, *wh, *wl;
    cudaGetSymbolAddress((void**)&ah, g_ah);
    cudaGetSymbolAddress((void**)&al, g_al);
    cudaGetSymbolAddress((void**)&wh, g_wh);
    cudaGetSymbolAddress((void**)&wl, g_wl);

    float* hn = out + (size_t)M_TOT * OUT_DIM;
    float* cn = hn + 2 * B_DIM * H_DIM;

    constexpr int SMEM64  = (128 + 64) * (64 + 8) * 2 * 2;    // 55,296 B
    constexpr int SMEM128 = (128 + 64) * (128 + 8) * 2 * 2;   // 104,448 B

    static bool attr_done = false;
    if (!attr_done) {
        cudaFuncSetAttribute(lstm_rec, cudaFuncAttributeMaxDynamicSharedMemorySize, REC_SMEM);
        cudaFuncSetAttribute(gemm_bf<IN_DIM>, cudaFuncAttributeMaxDynamicSharedMemorySize, SMEM64);
        cudaFuncSetAttribute(gemm_bf<H_DIM>,  cudaFuncAttributeMaxDynamicSharedMemorySize, SMEM128);
        attr_done = true;
    }

    dim3 gg(G_DIM / 64, M_TOT / 128);

    // ---- layer 0 (K = 64) ----
    {
        int n4a = M_TOT * IN_DIM / 4;
        conv_hl<<<(n4a + 255) / 256, 256>>>(x, ah, al, n4a);
        int n4w = G_DIM * IN_DIM / 4;
        conv_hl<<<(n4w + 255) / 256, 256>>>(w_ih0, wh, wl, n4w);
        gemm_bf<IN_DIM><<<gg, 256, SMEM64>>>(ah, al, wh, wl, xp);
        lstm_rec<<<B_DIM, 256, REC_SMEM>>>(xp, w_hh0, y, hn, cn);
    }
    // ---- layer 1 (K = 128) ----
    {
        int n4a = M_TOT * H_DIM / 4;
        conv_hl<<<(n4a + 255) / 256, 256>>>(y, ah, al, n4a);
        int n4w = G_DIM * H_DIM / 4;
        conv_hl<<<(n4w + 255) / 256, 256>>>(w_ih1, wh, wl, n4w);
        gemm_bf<H_DIM><<<gg, 256, SMEM128>>>(ah, al, wh, wl, xp);
        lstm_rec<<<B_DIM, 256, REC_SMEM>>>(xp, w_hh1, y, hn + B_DIM * H_DIM, cn + B_DIM * H_DIM);
    }
    // ---- FC head ----
    fc_head<<<M_TOT / 32, 256>>>(y, fc_w, fc_b, out);
}

// round 8
// speedup vs baseline: 1.5999x; 1.0799x over previous
#include <cuda_runtime.h>
#include <cuda_bf16.h>
#include <mma.h>
#include <cstdint>

using namespace nvcuda;

#define T_DIM   2048
#define B_DIM   128
#define IN_DIM  64
#define H_DIM   128
#define G_DIM   512
#define OUT_DIM 32
#define M_TOT   (T_DIM * B_DIM)   // 262144

typedef unsigned long long ull;

// scratch (device globals: allocation-free per harness rules)
__device__ __align__(16) float g_xp[(size_t)M_TOT * G_DIM];          // 512 MB
__device__ __align__(16) float g_y [(size_t)M_TOT * H_DIM];          // 128 MB
__device__ __align__(16) __nv_bfloat16 g_ah[(size_t)M_TOT * H_DIM];  // 64 MB
__device__ __align__(16) __nv_bfloat16 g_al[(size_t)M_TOT * H_DIM];  // 64 MB
__device__ __align__(16) __nv_bfloat16 g_wh[G_DIM * H_DIM];
__device__ __align__(16) __nv_bfloat16 g_wl[G_DIM * H_DIM];

// ---------------- activations ------------------------------------------------
__device__ __forceinline__ float tanh_f(float x) {
    float y; asm("tanh.approx.f32 %0, %1;" : "=f"(y) : "f"(x)); return y;
}
__device__ __forceinline__ float sigmoid_f(float x) {
    return 0.5f * tanh_f(0.5f * x) + 0.5f;
}
__device__ __forceinline__ ull fma2(ull a, ull b, ull c) {
    ull d; asm("fma.rn.f32x2 %0, %1, %2, %3;" : "=l"(d) : "l"(a), "l"(b), "l"(c));
    return d;
}
__device__ __forceinline__ float lo32(ull v) { return __uint_as_float((unsigned)(v & 0xffffffffu)); }
__device__ __forceinline__ float hi32(ull v) { return __uint_as_float((unsigned)(v >> 32)); }

// ---------------- fp32 -> bf16 hi/lo split (one elementwise pass) -----------
__global__ void __launch_bounds__(256) conv_hl(const float* __restrict__ src,
                                               __nv_bfloat16* __restrict__ dh,
                                               __nv_bfloat16* __restrict__ dl,
                                               int n4)
{
    int i = blockIdx.x * 256 + threadIdx.x;
    if (i >= n4) return;
    float4 v = reinterpret_cast<const float4*>(src)[i];
    __nv_bfloat162 h0, h1, l0, l1;
    h0.x = __float2bfloat16_rn(v.x); h0.y = __float2bfloat16_rn(v.y);
    h1.x = __float2bfloat16_rn(v.z); h1.y = __float2bfloat16_rn(v.w);
    l0.x = __float2bfloat16_rn(v.x - __bfloat162float(h0.x));
    l0.y = __float2bfloat16_rn(v.y - __bfloat162float(h0.y));
    l1.x = __float2bfloat16_rn(v.z - __bfloat162float(h1.x));
    l1.y = __float2bfloat16_rn(v.w - __bfloat162float(h1.y));
    union { __nv_bfloat162 b[2]; uint2 u2; } ph, pl;
    ph.b[0] = h0; ph.b[1] = h1; pl.b[0] = l0; pl.b[1] = l1;
    reinterpret_cast<uint2*>(dh)[i] = ph.u2;
    reinterpret_cast<uint2*>(dl)[i] = pl.u2;
}

// ---------------- bf16(hi+lo) tensor-core GEMM (pre-split inputs) -----------
template<int K>
__global__ void __launch_bounds__(256) gemm_bf(const __nv_bfloat16* __restrict__ Ah,
                                               const __nv_bfloat16* __restrict__ Al,
                                               const __nv_bfloat16* __restrict__ Wh,
                                               const __nv_bfloat16* __restrict__ Wl,
                                               float* __restrict__ C)
{
    constexpr int LD  = K + 8;
    constexpr int V8  = K / 8;
    extern __shared__ __nv_bfloat16 sb[];
    __nv_bfloat16* Ahs = sb;
    __nv_bfloat16* Als = Ahs + 128 * LD;
    __nv_bfloat16* Whs = Als + 128 * LD;
    __nv_bfloat16* Wls = Whs + 64 * LD;

    const int tid = threadIdx.x;
    const int m0 = blockIdx.y * 128, n0 = blockIdx.x * 64;

    #pragma unroll
    for (int i = tid; i < 128 * V8; i += 256) {
        int r = i / V8, c = i % V8;
        reinterpret_cast<uint4*>(Ahs + r * LD)[c] =
            *reinterpret_cast<const uint4*>(Ah + (size_t)(m0 + r) * K + c * 8);
        reinterpret_cast<uint4*>(Als + r * LD)[c] =
            *reinterpret_cast<const uint4*>(Al + (size_t)(m0 + r) * K + c * 8);
    }
    #pragma unroll
    for (int i = tid; i < 64 * V8; i += 256) {
        int r = i / V8, c = i % V8;
        reinterpret_cast<uint4*>(Whs + r * LD)[c] =
            *reinterpret_cast<const uint4*>(Wh + (size_t)(n0 + r) * K + c * 8);
        reinterpret_cast<uint4*>(Wls + r * LD)[c] =
            *reinterpret_cast<const uint4*>(Wl + (size_t)(n0 + r) * K + c * 8);
    }
    __syncthreads();

    const int warp = tid >> 5;
    const int wm = warp >> 1, wn = warp & 1;

    wmma::fragment<wmma::accumulator, 16, 16, 16, float> c[2][2];
    #pragma unroll
    for (int i = 0; i < 2; i++)
        #pragma unroll
        for (int j = 0; j < 2; j++) wmma::fill_fragment(c[i][j], 0.0f);

    #pragma unroll
    for (int k = 0; k < K; k += 16) {
        wmma::fragment<wmma::matrix_a, 16, 16, 16, __nv_bfloat16, wmma::row_major> fah[2], fal[2];
        wmma::fragment<wmma::matrix_b, 16, 16, 16, __nv_bfloat16, wmma::col_major> fbh[2], fbl[2];
        #pragma unroll
        for (int i = 0; i < 2; i++) {
            wmma::load_matrix_sync(fah[i], Ahs + (wm * 32 + 16 * i) * LD + k, LD);
            wmma::load_matrix_sync(fal[i], Als + (wm * 32 + 16 * i) * LD + k, LD);
            wmma::load_matrix_sync(fbh[i], Whs + (wn * 32 + 16 * i) * LD + k, LD);
            wmma::load_matrix_sync(fbl[i], Wls + (wn * 32 + 16 * i) * LD + k, LD);
        }
        #pragma unroll
        for (int i = 0; i < 2; i++)
            #pragma unroll
            for (int j = 0; j < 2; j++) {
                wmma::mma_sync(c[i][j], fal[i], fbh[j], c[i][j]);
                wmma::mma_sync(c[i][j], fah[i], fbl[j], c[i][j]);
                wmma::mma_sync(c[i][j], fah[i], fbh[j], c[i][j]);
            }
    }
    #pragma unroll
    for (int i = 0; i < 2; i++)
        #pragma unroll
        for (int j = 0; j < 2; j++)
            wmma::store_matrix_sync(C + (size_t)(m0 + wm * 32 + 16 * i) * G_DIM + (n0 + wn * 32 + 16 * j),
                                    c[i][j], G_DIM, wmma::mem_row_major);
}

// =============================================================================
// LSTM recurrence v3: lane-pair k-split, 1 barrier/step.
// grid = 128 CTAs (one per batch), 256 threads = 8 warps.
// Warp w, lane l: cell m = w*16 + (l&15); half = l>>4 selects k range:
//   half 0: k in [0,64), half 1: k in [64,128).
// Each thread computes PARTIAL sums for all 4 gates (i,f,g,o) of cell m over
// its k-half. k-half layout: first 48 k in registers (24 ull per gate),
// last 16 k in smem. Partials merged via 4x shfl_xor(16); only half==0 lanes
// run activations / c / h and store. h double-buffered; t-loop unrolled x2
// for static buffer offsets; ONE __syncthreads per step.
// smem: ws2 [4c][4g][2half][128m] ulonglong2 = 65536 B | hbuf [2][128] f32
// =============================================================================
#define REC_SMEM (65536 + 2 * 128 * 4)

__global__ void __launch_bounds__(256, 1) lstm_rec(const float* __restrict__ xp,
                                                   const float* __restrict__ whh,
                                                   float* __restrict__ y,
                                                   float* __restrict__ hn,
                                                   float* __restrict__ cn)
{
    extern __shared__ __align__(16) char smraw[];
    ulonglong2* ws2  = reinterpret_cast<ulonglong2*>(smraw);      // [4][4][2][128]
    float*      hbuf = reinterpret_cast<float*>(smraw + 65536);   // [2][128]

    const int b    = blockIdx.x;
    const int tid  = threadIdx.x;
    const int lane = tid & 31;
    const int w    = tid >> 5;
    const int half = lane >> 4;
    const int m    = w * 16 + (lane & 15);
    const int ko   = half * 64;

    // ---- load weights: 4 gate rows for cell m, this k-half ----
    ull wreg[4][24];
    #pragma unroll
    for (int g = 0; g < 4; g++) {
        const ull* wp = reinterpret_cast<const ull*>(whh + (size_t)(g * 128 + m) * H_DIM + ko);
        #pragma unroll
        for (int u = 0; u < 24; u++) wreg[g][u] = wp[u];
        const ulonglong2* wp2 = reinterpret_cast<const ulonglong2*>(wp + 24);
        #pragma unroll
        for (int c = 0; c < 4; c++)
            ws2[((c * 4 + g) * 2 + half) * 128 + m] = wp2[c];
    }
    if (tid < H_DIM) hbuf[tid] = 0.0f;
    float cst = 0.0f, hlast = 0.0f;
    __syncthreads();

    // xp rows: half 0 -> i (m), f (m+128); half 1 -> g (m+256), o (m+384)
    const float* xq0 = xp + (size_t)b * G_DIM + (half ? (m + 256) : m);
    const float* xq1 = xp + (size_t)b * G_DIM + (half ? (m + 384) : (m + 128));
    float xv0 = xq0[0], xv1 = xq1[0];

#define LSTM_STEP(T, RDOFF, WROFF)                                              \
    {                                                                           \
        const ulonglong2* h2 = reinterpret_cast<const ulonglong2*>(hbuf + (RDOFF)) + half * 16; \
        float xn0 = 0.0f, xn1 = 0.0f;                                           \
        if ((T) + 1 < T_DIM) {                                                  \
            size_t off = (size_t)((T) + 1) * B_DIM * G_DIM;                     \
            xn0 = xq0[off]; xn1 = xq1[off];                                     \
        }                                                                       \
        ull a0 = 0, a1 = 0, a2 = 0, a3 = 0;                                     \
        _Pragma("unroll")                                                       \
        for (int c = 0; c < 12; c++) {                                          \
            ulonglong2 hv = h2[c];                                              \
            a0 = fma2(wreg[0][2 * c], hv.x, a0); a0 = fma2(wreg[0][2 * c + 1], hv.y, a0); \
            a1 = fma2(wreg[1][2 * c], hv.x, a1); a1 = fma2(wreg[1][2 * c + 1], hv.y, a1); \
            a2 = fma2(wreg[2][2 * c], hv.x, a2); a2 = fma2(wreg[2][2 * c + 1], hv.y, a2); \
            a3 = fma2(wreg[3][2 * c], hv.x, a3); a3 = fma2(wreg[3][2 * c + 1], hv.y, a3); \
        }                                                                       \
        _Pragma("unroll")                                                       \
        for (int c = 0; c < 4; c++) {                                           \
            ulonglong2 hv = h2[12 + c];                                         \
            ulonglong2 w0 = ws2[((c * 4 + 0) * 2 + half) * 128 + m];            \
            ulonglong2 w1 = ws2[((c * 4 + 1) * 2 + half) * 128 + m];            \
            ulonglong2 w2 = ws2[((c * 4 + 2) * 2 + half) * 128 + m];            \
            ulonglong2 w3 = ws2[((c * 4 + 3) * 2 + half) * 128 + m];            \
            a0 = fma2(w0.x, hv.x, a0); a0 = fma2(w0.y, hv.y, a0);               \
            a1 = fma2(w1.x, hv.x, a1); a1 = fma2(w1.y, hv.y, a1);               \
            a2 = fma2(w2.x, hv.x, a2); a2 = fma2(w2.y, hv.y, a2);               \
            a3 = fma2(w3.x, hv.x, a3); a3 = fma2(w3.y, hv.y, a3);               \
        }                                                                       \
        float p0 = lo32(a0) + hi32(a0);                                         \
        float p1 = lo32(a1) + hi32(a1);                                         \
        float p2 = lo32(a2) + hi32(a2);                                         \
        float p3 = lo32(a3) + hi32(a3);                                         \
        if (half) { p2 += xv0; p3 += xv1; } else { p0 += xv0; p1 += xv1; }      \
        float q0 = __shfl_xor_sync(0xffffffffu, p0, 16);                        \
        float q1 = __shfl_xor_sync(0xffffffffu, p1, 16);                        \
        float q2 = __shfl_xor_sync(0xffffffffu, p2, 16);                        \
        float q3 = __shfl_xor_sync(0xffffffffu, p3, 16);                        \
        if (!half) {                                                            \
            float ig = sigmoid_f(p0 + q0);                                      \
            float fg = sigmoid_f(p1 + q1);                                      \
            float ga = tanh_f(p2 + q2);                                         \
            float og = sigmoid_f(p3 + q3);                                      \
            cst = fg * cst + ig * ga;                                           \
            float h = og * tanh_f(cst);                                         \
            hlast = h;                                                          \
            hbuf[(WROFF) + m] = h;                                              \
            y[((size_t)(T) * B_DIM + b) * H_DIM + m] = h;                       \
        }                                                                       \
        __syncthreads();                                                        \
        xv0 = xn0; xv1 = xn1;                                                   \
    }

    for (int t = 0; t < T_DIM; t += 2) {
        LSTM_STEP(t,     0,   128);
        LSTM_STEP(t + 1, 128, 0);
    }
#undef LSTM_STEP

    if (!half) {
        hn[b * H_DIM + m] = hlast;
        cn[b * H_DIM + m] = cst;
    }
}

// ---------------- FC head ----------------------------------------------------
__global__ void __launch_bounds__(256) fc_head(const float* __restrict__ A,
                                               const float* __restrict__ W,
                                               const float* __restrict__ bias,
                                               float* __restrict__ C)
{
    __shared__ float ys[32][128];
    __shared__ float wst[128][32];
    const int tid = threadIdx.x;
    const int m0 = blockIdx.x * 32;

    for (int i = tid; i < OUT_DIM * H_DIM; i += 256) {
        int o = i / H_DIM, k = i % H_DIM;
        wst[k][o] = W[i];
    }
    for (int i = tid; i < 32 * H_DIM; i += 256) {
        int r = i / H_DIM, k = i % H_DIM;
        ys[r][k] = A[(size_t)(m0 + r) * H_DIM + k];
    }
    __syncthreads();

    const int o = tid & 31, mq = tid >> 5;
    float a0 = 0.f, a1 = 0.f, a2 = 0.f, a3 = 0.f;
    #pragma unroll 8
    for (int k = 0; k < H_DIM; k++) {
        float w = wst[k][o];
        a0 += ys[mq * 4 + 0][k] * w;
        a1 += ys[mq * 4 + 1][k] * w;
        a2 += ys[mq * 4 + 2][k] * w;
        a3 += ys[mq * 4 + 3][k] * w;
    }
    float bb = bias[o];
    C[(size_t)(m0 + mq * 4 + 0) * OUT_DIM + o] = a0 + bb;
    C[(size_t)(m0 + mq * 4 + 1) * OUT_DIM + o] = a1 + bb;
    C[(size_t)(m0 + mq * 4 + 2) * OUT_DIM + o] = a2 + bb;
    C[(size_t)(m0 + mq * 4 + 3) * OUT_DIM + o] = a3 + bb;
}

extern "C" void kernel_launch(void* const* d_in, const int* in_sizes, int n_in,
                              void* d_out, int out_size)
{
    const float* x     = (const float*)d_in[0];
    const float* w_ih0 = (const float*)d_in[1];
    const float* w_hh0 = (const float*)d_in[2];
    const float* w_ih1 = (const float*)d_in[3];
    const float* w_hh1 = (const float*)d_in[4];
    const float* fc_w  = (const float*)d_in[5];
    const float* fc_b  = (const float*)d_in[6];
    float* out = (float*)d_out;

    float* xp; cudaGetSymbolAddress((void**)&xp, g_xp);
    float* y;  cudaGetSymbolAddress((void**)&y,  g_y);
    __nv_bfloat16 *ah, *al, *wh, *wl;
    cudaGetSymbolAddress((void**)&ah, g_ah);
    cudaGetSymbolAddress((void**)&al, g_al);
    cudaGetSymbolAddress((void**)&wh, g_wh);
    cudaGetSymbolAddress((void**)&wl, g_wl);

    float* hn = out + (size_t)M_TOT * OUT_DIM;
    float* cn = hn + 2 * B_DIM * H_DIM;

    constexpr int SMEM64  = (128 + 64) * (64 + 8) * 2 * 2;    // 55,296 B
    constexpr int SMEM128 = (128 + 64) * (128 + 8) * 2 * 2;   // 104,448 B

    static bool attr_done = false;
    if (!attr_done) {
        cudaFuncSetAttribute(lstm_rec, cudaFuncAttributeMaxDynamicSharedMemorySize, REC_SMEM);
        cudaFuncSetAttribute(gemm_bf<IN_DIM>, cudaFuncAttributeMaxDynamicSharedMemorySize, SMEM64);
        cudaFuncSetAttribute(gemm_bf<H_DIM>,  cudaFuncAttributeMaxDynamicSharedMemorySize, SMEM128);
        attr_done = true;
    }

    dim3 gg(G_DIM / 64, M_TOT / 128);

    // ---- layer 0 (K = 64) ----
    {
        int n4a = M_TOT * IN_DIM / 4;
        conv_hl<<<(n4a + 255) / 256, 256>>>(x, ah, al, n4a);
        int n4w = G_DIM * IN_DIM / 4;
        conv_hl<<<(n4w + 255) / 256, 256>>>(w_ih0, wh, wl, n4w);
        gemm_bf<IN_DIM><<<gg, 256, SMEM64>>>(ah, al, wh, wl, xp);
        lstm_rec<<<B_DIM, 256, REC_SMEM>>>(xp, w_hh0, y, hn, cn);
    }
    // ---- layer 1 (K = 128) ----
    {
        int n4a = M_TOT * H_DIM / 4;
        conv_hl<<<(n4a + 255) / 256, 256>>>(y, ah, al, n4a);
        int n4w = G_DIM * H_DIM / 4;
        conv_hl<<<(n4w + 255) / 256, 256>>>(w_ih1, wh, wl, n4w);
        gemm_bf<H_DIM><<<gg, 256, SMEM128>>>(ah, al, wh, wl, xp);
        lstm_rec<<<B_DIM, 256, REC_SMEM>>>(xp, w_hh1, y, hn + B_DIM * H_DIM, cn + B_DIM * H_DIM);
    }
    // ---- FC head ----
    fc_head<<<M_TOT / 32, 256>>>(y, fc_w, fc_b, out);
}